// round 17
// baseline (speedup 1.0000x reference)
#include <cuda_runtime.h>
#include <cuda_bf16.h>
#include <cuda_fp16.h>
#include <cstdint>

#define D        256
#define TILE_M   64
#define KNBR     16
#define NTHREADS 256
#define LN_EPS   1e-5f
#define N_MAX    50000

// A smem: bf16, row stride 264 elems = 528 B (skewed, conflict-free fragment LDS).
#define AS        264
#define SM_A_HI   0
#define SM_A_LO   (TILE_M * AS * 2)               // 33792
#define SM_TOTAL  (SM_A_LO + TILE_M * AS * 2)     // 67584 B (2 CTAs/SM)

// ============ device globals ============
__device__ int g_idx_is64;
// W transposed + hi/lo bf16 split, packed in mma.sync B-fragment order.
__device__ uint16_t g_Bhi[D * D];
__device__ uint16_t g_Blo[D * D];
// T = F @ W + b, fp16  (the gather target; L2-resident at 25.6 MB)
__device__ __half g_T[(size_t)N_MAX * D];

// Prep: W fragment-pack + idx-width detect (int64 storage has zero odd words).
__global__ void prep_kernel(const float* __restrict__ W,
                            const int*   __restrict__ nbr32,
                            int n_words)
{
    const int gtid = blockIdx.x * blockDim.x + threadIdx.x;
    if (gtid < D * D) {
        const int k = gtid >> 8, n = gtid & 255;
        const float w = W[(size_t)k * D + n];
        const __nv_bfloat16 hi = __float2bfloat16(w);
        const float lo = w - __bfloat162float(hi);
        const int kb = k >> 4, nb = n >> 3, kl = k & 15, nl = n & 7;
        const int ln  = nl * 4 + ((kl & 7) >> 1);
        const int off = ((nb * 16 + kb) * 32 + ln) * 4 + ((kl >> 3) << 1) + (kl & 1);
        g_Bhi[off] = __bfloat16_as_ushort(hi);
        g_Blo[off] = __bfloat16_as_ushort(__float2bfloat16(lo));
    }
    if (blockIdx.x == 0) {
        __shared__ int any_nonzero;
        if (threadIdx.x == 0) any_nonzero = 0;
        __syncthreads();
        for (int i = threadIdx.x; i < n_words / 2; i += blockDim.x)
            if (nbr32[2 * i + 1] != 0) any_nonzero = 1;
        __syncthreads();
        if (threadIdx.x == 0) g_idx_is64 = (any_nonzero == 0) ? 1 : 0;
    }
}

#define MMA_BF16(d, a0, a1, a2, a3, b0, b1) \
    asm volatile("mma.sync.aligned.m16n8k16.row.col.f32.bf16.bf16.f32 " \
        "{%0,%1,%2,%3}, {%4,%5,%6,%7}, {%8,%9}, {%0,%1,%2,%3};" \
        : "+f"(d[0]), "+f"(d[1]), "+f"(d[2]), "+f"(d[3]) \
        : "r"(a0), "r"(a1), "r"(a2), "r"(a3), "r"(b0), "r"(b1))

__device__ __forceinline__ uint32_t pack_bf16x2(float lo_col, float hi_col) {
    uint32_t r;
    asm("cvt.rn.bf16x2.f32 %0, %1, %2;" : "=r"(r) : "f"(hi_col), "f"(lo_col));
    return r;
}

// ============ Kernel B: dense GEMM  T = F @ W + b  (fp16 out) ============
__global__ void __launch_bounds__(NTHREADS, 2)
dense_gemm_kernel(const float* __restrict__ F,
                  const float* __restrict__ bias_p,
                  int N)
{
    extern __shared__ char smem[];
    uint16_t* Ah = (uint16_t*)(smem + SM_A_HI);
    uint16_t* Al = (uint16_t*)(smem + SM_A_LO);

    const int tid  = threadIdx.x;
    const int warp = tid >> 5;
    const int lane = tid & 31;
    const int tile0 = blockIdx.x * TILE_M;

    // ---- Phase 1: coalesced F load -> bf16 hi/lo smem tile (8 rows/warp) ----
    for (int i = 0; i < 8; ++i) {
        const int r = warp * 8 + i;
        const int g = tile0 + r;
        float v[8] = {0.f, 0.f, 0.f, 0.f, 0.f, 0.f, 0.f, 0.f};
        if (g < N) {
            const float4 a = *((const float4*)(F + (size_t)g * D) + 2 * lane);
            const float4 b = *((const float4*)(F + (size_t)g * D) + 2 * lane + 1);
            v[0] = a.x; v[1] = a.y; v[2] = a.z; v[3] = a.w;
            v[4] = b.x; v[5] = b.y; v[6] = b.z; v[7] = b.w;
        }
        uint32_t hw[4], lw[4];
        #pragma unroll
        for (int p = 0; p < 4; ++p) {
            const float x0 = v[2 * p], x1 = v[2 * p + 1];
            const __nv_bfloat16 b0 = __float2bfloat16(x0);
            const __nv_bfloat16 b1 = __float2bfloat16(x1);
            hw[p] = (uint32_t)__bfloat16_as_ushort(b0) |
                    ((uint32_t)__bfloat16_as_ushort(b1) << 16);
            lw[p] = pack_bf16x2(x0 - __bfloat162float(b0), x1 - __bfloat162float(b1));
        }
        *(uint4*)&Ah[r * AS + 8 * lane] = make_uint4(hw[0], hw[1], hw[2], hw[3]);
        *(uint4*)&Al[r * AS + 8 * lane] = make_uint4(lw[0], lw[1], lw[2], lw[3]);
    }
    __syncthreads();

    // ---- Phase 2: GEMM via mma.sync; warp grid 2m x 4n, warp tile 32x64 ----
    const int wm  = warp >> 2;
    const int wnp = warp & 3;
    const int g8  = lane >> 2;
    const int c2  = (lane & 3) * 2;

    float acc[2][8][4];
    #pragma unroll
    for (int mi = 0; mi < 2; ++mi)
        #pragma unroll
        for (int nb = 0; nb < 8; ++nb)
            #pragma unroll
            for (int q = 0; q < 4; ++q) acc[mi][nb][q] = 0.f;

    const uint2* Bh = (const uint2*)g_Bhi;
    const uint2* Bl = (const uint2*)g_Blo;

    for (int ks = 0; ks < 16; ++ks) {
        const int k0 = ks * 16;
        uint32_t ah[2][4], al[2][4];
        #pragma unroll
        for (int mi = 0; mi < 2; ++mi) {
            const int base = (wm * 32 + mi * 16 + g8) * AS + k0 + c2;
            ah[mi][0] = *(const uint32_t*)&Ah[base];
            ah[mi][1] = *(const uint32_t*)&Ah[base + 8 * AS];
            ah[mi][2] = *(const uint32_t*)&Ah[base + 8];
            ah[mi][3] = *(const uint32_t*)&Ah[base + 8 * AS + 8];
            al[mi][0] = *(const uint32_t*)&Al[base];
            al[mi][1] = *(const uint32_t*)&Al[base + 8 * AS];
            al[mi][2] = *(const uint32_t*)&Al[base + 8];
            al[mi][3] = *(const uint32_t*)&Al[base + 8 * AS + 8];
        }
        #pragma unroll
        for (int nb = 0; nb < 8; ++nb) {
            const int bidx = (((wnp * 8 + nb) * 16) + ks) * 32 + lane;
            const uint2 bh = __ldg(&Bh[bidx]);
            const uint2 bl = __ldg(&Bl[bidx]);
            #pragma unroll
            for (int mi = 0; mi < 2; ++mi) {
                MMA_BF16(acc[mi][nb], ah[mi][0], ah[mi][1], ah[mi][2], ah[mi][3], bh.x, bh.y);
                MMA_BF16(acc[mi][nb], ah[mi][0], ah[mi][1], ah[mi][2], ah[mi][3], bl.x, bl.y);
                MMA_BF16(acc[mi][nb], al[mi][0], al[mi][1], al[mi][2], al[mi][3], bh.x, bh.y);
            }
        }
    }

    // ---- Phase 3: +bias, store T fp16 ----
    #pragma unroll
    for (int mi = 0; mi < 2; ++mi) {
        const int rLa = wm * 32 + mi * 16 + g8;
        const int gA = tile0 + rLa;
        const int gB = gA + 8;
        #pragma unroll
        for (int nb = 0; nb < 8; ++nb) {
            const int col0 = wnp * 64 + nb * 8 + c2;
            const float b0 = __ldg(bias_p + col0);
            const float b1 = __ldg(bias_p + col0 + 1);
            const float* a = acc[mi][nb];
            if (gA < N)
                *(__half2*)&g_T[(size_t)gA * D + col0] =
                    __floats2half2_rn(a[0] + b0, a[1] + b1);
            if (gB < N)
                *(__half2*)&g_T[(size_t)gB * D + col0] =
                    __floats2half2_rn(a[2] + b0, a[3] + b1);
        }
    }
}

// ============ Kernel C: gather + weighted sum + LayerNorm (1 warp/node) ============
__global__ void __launch_bounds__(256)
gather_ln_kernel(const void*  __restrict__ neighbors_raw,
                 const float* __restrict__ weights,
                 const float* __restrict__ gamma,
                 const float* __restrict__ beta,
                 float*       __restrict__ out,
                 int N)
{
    const int warp = threadIdx.x >> 5;
    const int lane = threadIdx.x & 31;
    const int node = blockIdx.x * 8 + warp;
    if (node >= N) return;

    const int idx_is64 = g_idx_is64;
    const int*       nbr32 = (const int*)neighbors_raw;
    const long long* nbr64 = (const long long*)neighbors_raw;

    int   nb = 0;
    float w  = 0.f;
    if (lane < KNBR) {
        const size_t pos = (size_t)node * KNBR + lane;
        nb = idx_is64 ? (int)nbr64[pos] : nbr32[pos];
        nb = min(max(nb, 0), N - 1);
        w  = weights[pos];
    }
    float wsum = w;
    #pragma unroll
    for (int s = 16; s; s >>= 1) wsum += __shfl_xor_sync(0xffffffffu, wsum, s);
    const float wn = (wsum == 0.f) ? (1.0f / KNBR) : (w / wsum);

    // weighted gather of T rows: lane covers cols 8*lane..8*lane+7
    float acc[8] = {0.f, 0.f, 0.f, 0.f, 0.f, 0.f, 0.f, 0.f};
    #pragma unroll
    for (int k = 0; k < KNBR; ++k) {
        const int   idx = __shfl_sync(0xffffffffu, nb, k);
        const float wk  = __shfl_sync(0xffffffffu, wn, k);
        const uint4 v = *((const uint4*)(g_T + (size_t)idx * D) + lane);
        const __half2* h2 = (const __half2*)&v;
        #pragma unroll
        for (int p = 0; p < 4; ++p) {
            const float2 f = __half22float2(h2[p]);
            acc[2 * p]     += wk * f.x;
            acc[2 * p + 1] += wk * f.y;
        }
    }

    // LayerNorm over the 256 cols (8 per lane)
    float s = 0.f, sq = 0.f;
    #pragma unroll
    for (int j = 0; j < 8; ++j) { s += acc[j]; sq += acc[j] * acc[j]; }
    #pragma unroll
    for (int o = 16; o; o >>= 1) {
        s  += __shfl_xor_sync(0xffffffffu, s,  o);
        sq += __shfl_xor_sync(0xffffffffu, sq, o);
    }
    const float mean = s * (1.0f / D);
    const float var  = sq * (1.0f / D) - mean * mean;
    const float rstd = rsqrtf(var + LN_EPS);

    float o0[4], o1[4];
    #pragma unroll
    for (int j = 0; j < 8; ++j) {
        const int c = 8 * lane + j;
        const float r = (acc[j] - mean) * rstd * __ldg(gamma + c) + __ldg(beta + c);
        if (j < 4) o0[j] = r; else o1[j - 4] = r;
    }
    float* op = out + (size_t)node * D + 8 * lane;
    *(float4*)op       = make_float4(o0[0], o0[1], o0[2], o0[3]);
    *(float4*)(op + 4) = make_float4(o1[0], o1[1], o1[2], o1[3]);
}

extern "C" void kernel_launch(void* const* d_in, const int* in_sizes, int n_in,
                              void* d_out, int out_size)
{
    const float* features  = (const float*)d_in[0];
    const void*  neighbors = (const void*)d_in[1];
    const float* weights   = (const float*)d_in[2];
    const float* W         = (const float*)d_in[3];
    const float* bias_p    = (const float*)d_in[4];
    const float* gamma     = (const float*)d_in[5];
    const float* beta      = (const float*)d_in[6];
    float*       out       = (float*)d_out;

    const int N = in_sizes[0] / D;        // 50000
    const int n_idx_elems = in_sizes[1];
    const int check_words = n_idx_elems < 4096 ? n_idx_elems : 4096;

    prep_kernel<<<(D * D + 255) / 256, 256>>>(W, (const int*)neighbors, check_words);

    cudaFuncSetAttribute(dense_gemm_kernel,
                         cudaFuncAttributeMaxDynamicSharedMemorySize, SM_TOTAL);
    dense_gemm_kernel<<<(N + TILE_M - 1) / TILE_M, NTHREADS, SM_TOTAL>>>(
        features, bias_p, N);

    gather_ln_kernel<<<(N + 7) / 8, 256>>>(
        neighbors, weights, gamma, beta, out, N);
}